// round 11
// baseline (speedup 1.0000x reference)
#include <cuda_runtime.h>
#include <stdint.h>

// VTM downsampler — 16 output rows/block via 7-slot ROTATING horizontal registers.
// 9 staged rows / 9 HROWs per 16 output rows (vs 14 for two 8-row blocks),
// while live register state stays at 7 slots x 4 chains = 28 floats (R6 level).
//
// Exact: all intermediates integer-valued * 2^-14 (or 2^-7 for the phase-0
// column); |units| < 2^24 -> fp32-exact. v = (m+8192)*2^-14 exactly, so
// cvt.rzi.sat.u8(v) == clip(floor(v),0,255).
//
// integer = i>>2, frac = 4*(i&3) -> FILTER rows {0,4,8,12}, taps k=3..8.
// Chunk B: output rows 16B..16B+15; band g (0..3) uses local input rows g..g+5,
// local row r lives in slot r%7.

#define IH 1080
#define IW 1920
#define OH 540
#define OW 960
#define NIMG 24
#define XC 245           // staged cols: gcol -2..242 at local 0..244
#define XCP 248
#define NRS 9            // staged rows: 4B-2 .. 4B+6

#define S14 6.103515625e-5f   // 2^-14
#define S7  7.8125e-3f        // 2^-7 (phase-0 column: 128x folded in)

// horizontal 6-tap (integer-valued results, exact in fp32)
#define HP1(a,b,c,d,e,f) fmaf(5.f,(a), fmaf(-18.f,(b), fmaf(114.f,(c), fmaf(36.f,(d), fmaf(-10.f,(e),(f))))))
#define HP2(a,b,c,d,e,f) fmaf(4.f,((a)+(f)), fmaf(-19.f,((b)+(e)), 79.f*((c)+(d))))
#define HP3(a,b,c,d,e,f) fmaf(5.f,(f), fmaf(-18.f,(e), fmaf(114.f,(d), fmaf(36.f,(c), fmaf(-10.f,(b),(a))))))

// vertical 6-tap chains over explicit slots, coeffs pre-scaled, bias 0.5 seeded
#define WD(h,S,s2)                 fmaf(128.f*(S), h[s2], 0.5f)
#define W1(h,S,s0,s1,s2,s3,s4,s5) fmaf(5.f*(S),h[s0], fmaf(-18.f*(S),h[s1], fmaf(114.f*(S),h[s2], \
                                   fmaf(36.f*(S),h[s3], fmaf(-10.f*(S),h[s4], fmaf((S),h[s5],0.5f))))))
#define W2(h,S,s0,s1,s2,s3,s4,s5) fmaf(4.f*(S),(h[s0]+h[s5]), fmaf(-19.f*(S),(h[s1]+h[s4]), \
                                   fmaf(79.f*(S),(h[s2]+h[s3]),0.5f)))
#define W3(h,S,s0,s1,s2,s3,s4,s5) fmaf(5.f*(S),h[s5], fmaf(-18.f*(S),h[s4], fmaf(114.f*(S),h[s3], \
                                   fmaf(36.f*(S),h[s2], fmaf(-10.f*(S),h[s1], fmaf((S),h[s0],0.5f))))))

// clip(floor(v),0,255) via saturating u8 truncate
__device__ __forceinline__ float fin(float v) {
    unsigned short t; asm("cvt.rzi.sat.u8.f32 %0,%1;" : "=h"(t) : "f"(v));
    float o;          asm("cvt.rn.f32.u8 %0,%1;" : "=f"(o) : "h"(t));
    return o;
}

// horizontal filters for staged row r into slot s
#define HROW(r, s) do { \
    const float a = xt[r][tid];     \
    const float b = xt[r][tid + 1]; \
    const float c = xt[r][tid + 2]; \
    const float d = xt[r][tid + 3]; \
    const float e = xt[r][tid + 4]; \
    const float f = xt[r][tid + 5]; \
    cv[s] = c; \
    h1[s] = HP1(a, b, c, d, e, f); \
    h2[s] = HP2(a, b, c, d, e, f); \
    h3[s] = HP3(a, b, c, d, e, f); \
} while (0)

// emit one 4-row output band from slots s0..s5, at output-row offset ro
#define BAND(s0,s1,s2,s3,s4,s5, ro) do { \
    float* op = oim + (ro) * OW; \
    float4 o; \
    o.x = cv[s2]; \
    o.y = fin(WD(h1,S14,s2)); o.z = fin(WD(h2,S14,s2)); o.w = fin(WD(h3,S14,s2)); \
    *(float4*)op = o; \
    o.x = fin(W1(cv,S7, s0,s1,s2,s3,s4,s5)); o.y = fin(W1(h1,S14,s0,s1,s2,s3,s4,s5)); \
    o.z = fin(W1(h2,S14,s0,s1,s2,s3,s4,s5)); o.w = fin(W1(h3,S14,s0,s1,s2,s3,s4,s5)); \
    *(float4*)(op + OW) = o; \
    o.x = fin(W2(cv,S7, s0,s1,s2,s3,s4,s5)); o.y = fin(W2(h1,S14,s0,s1,s2,s3,s4,s5)); \
    o.z = fin(W2(h2,S14,s0,s1,s2,s3,s4,s5)); o.w = fin(W2(h3,S14,s0,s1,s2,s3,s4,s5)); \
    *(float4*)(op + 2 * OW) = o; \
    o.x = fin(W3(cv,S7, s0,s1,s2,s3,s4,s5)); o.y = fin(W3(h1,S14,s0,s1,s2,s3,s4,s5)); \
    o.z = fin(W3(h2,S14,s0,s1,s2,s3,s4,s5)); o.w = fin(W3(h3,S14,s0,s1,s2,s3,s4,s5)); \
    *(float4*)(op + 3 * OW) = o; \
} while (0)

__global__ __launch_bounds__(240, 6)
void vtm_down_kernel(const float* __restrict__ x, float* __restrict__ out) {
    const int bc = blockIdx.y;            // image 0..23
    const int B  = blockIdx.x;            // 16-output-row chunk, 0..33

    __shared__ float xt[NRS][XCP];

    const int tid = threadIdx.x;          // 0..239 : output-col tile
    const float* xim = x + bc * (IH * IW);      // all offsets < 2^31
    const int r0 = 4 * B - 2;             // global input row of local 0

    // ---- stage 9 x 245 clamped input window ----
    const int c0 = tid - 2 < 0 ? 0 : tid - 2;   // left clamp (tid<2 only)
    #pragma unroll
    for (int r = 0; r < NRS; r++) {
        int gr = r0 + r; if (gr < 0) gr = 0;    // top clamp (B==0 only)
        const float* row = xim + gr * IW;
        xt[r][tid] = __ldg(&row[c0]);
        if (tid < XC - 240) xt[r][240 + tid] = __ldg(&row[238 + tid]);
    }
    __syncthreads();

    float cv[7], h1[7], h2[7], h3[7];
    float* oim = out + bc * (OH * OW) + (16 * B) * OW + tid * 4;

    // rows 0..5 -> slots 0..5, emit band0; row6 -> slot6, band1;
    // row7 -> slot0, band2; row8 -> slot1, band3 (skipped for B==33).
    HROW(0, 0); HROW(1, 1); HROW(2, 2); HROW(3, 3); HROW(4, 4); HROW(5, 5);
    BAND(0, 1, 2, 3, 4, 5, 0);
    HROW(6, 6);
    BAND(1, 2, 3, 4, 5, 6, 4);
    HROW(7, 0);
    BAND(2, 3, 4, 5, 6, 0, 8);
    if (B < 33) {
        HROW(8, 1);
        BAND(3, 4, 5, 6, 0, 1, 12);
    }
}

extern "C" void kernel_launch(void* const* d_in, const int* in_sizes, int n_in,
                              void* d_out, int out_size) {
    const float* x = (const float*)d_in[0];
    float* out = (float*)d_out;
    dim3 grid(34, NIMG);                  // 816 blocks <= 888 resident: one wave
    vtm_down_kernel<<<grid, 240>>>(x, out);
}

// round 12
// speedup vs baseline: 1.0650x; 1.0650x over previous
#include <cuda_runtime.h>
#include <stdint.h>

// VTM downsampler — 16 output rows/block via 7-slot ROTATING horizontal registers.
// 9 staged rows / 9 HROWs per 16 output rows (vs 14 for two 8-row blocks),
// while live register state stays at 7 slots x 4 chains = 28 floats (R6 level).
//
// Exact: all intermediates integer-valued * 2^-14 (or 2^-7 for the phase-0
// column); |units| < 2^24 -> fp32-exact. v = (m+8192)*2^-14 exactly, so
// cvt.rzi.sat.u8(v) == clip(floor(v),0,255).
//
// integer = i>>2, frac = 4*(i&3) -> FILTER rows {0,4,8,12}, taps k=3..8.
// Chunk B: output rows 16B..16B+15; band g (0..3) uses local input rows g..g+5,
// local row r lives in slot r%7.

#define IH 1080
#define IW 1920
#define OH 540
#define OW 960
#define NIMG 24
#define XC 245           // staged cols: gcol -2..242 at local 0..244
#define XCP 248
#define NRS 9            // staged rows: 4B-2 .. 4B+6

#define S14 6.103515625e-5f   // 2^-14
#define S7  7.8125e-3f        // 2^-7 (phase-0 column: 128x folded in)

// horizontal 6-tap (integer-valued results, exact in fp32)
#define HP1(a,b,c,d,e,f) fmaf(5.f,(a), fmaf(-18.f,(b), fmaf(114.f,(c), fmaf(36.f,(d), fmaf(-10.f,(e),(f))))))
#define HP2(a,b,c,d,e,f) fmaf(4.f,((a)+(f)), fmaf(-19.f,((b)+(e)), 79.f*((c)+(d))))
#define HP3(a,b,c,d,e,f) fmaf(5.f,(f), fmaf(-18.f,(e), fmaf(114.f,(d), fmaf(36.f,(c), fmaf(-10.f,(b),(a))))))

// vertical 6-tap chains over explicit slots, coeffs pre-scaled, bias 0.5 seeded
#define WD(h,S,s2)                 fmaf(128.f*(S), h[s2], 0.5f)
#define W1(h,S,s0,s1,s2,s3,s4,s5) fmaf(5.f*(S),h[s0], fmaf(-18.f*(S),h[s1], fmaf(114.f*(S),h[s2], \
                                   fmaf(36.f*(S),h[s3], fmaf(-10.f*(S),h[s4], fmaf((S),h[s5],0.5f))))))
#define W2(h,S,s0,s1,s2,s3,s4,s5) fmaf(4.f*(S),(h[s0]+h[s5]), fmaf(-19.f*(S),(h[s1]+h[s4]), \
                                   fmaf(79.f*(S),(h[s2]+h[s3]),0.5f)))
#define W3(h,S,s0,s1,s2,s3,s4,s5) fmaf(5.f*(S),h[s5], fmaf(-18.f*(S),h[s4], fmaf(114.f*(S),h[s3], \
                                   fmaf(36.f*(S),h[s2], fmaf(-10.f*(S),h[s1], fmaf((S),h[s0],0.5f))))))

// clip(floor(v),0,255) via saturating u8 truncate
__device__ __forceinline__ float fin(float v) {
    unsigned short t; asm("cvt.rzi.sat.u8.f32 %0,%1;" : "=h"(t) : "f"(v));
    float o;          asm("cvt.rn.f32.u8 %0,%1;" : "=f"(o) : "h"(t));
    return o;
}

// horizontal filters for staged row r into slot s
#define HROW(r, s) do { \
    const float a = xt[r][tid];     \
    const float b = xt[r][tid + 1]; \
    const float c = xt[r][tid + 2]; \
    const float d = xt[r][tid + 3]; \
    const float e = xt[r][tid + 4]; \
    const float f = xt[r][tid + 5]; \
    cv[s] = c; \
    h1[s] = HP1(a, b, c, d, e, f); \
    h2[s] = HP2(a, b, c, d, e, f); \
    h3[s] = HP3(a, b, c, d, e, f); \
} while (0)

// emit one 4-row output band from slots s0..s5, at output-row offset ro
#define BAND(s0,s1,s2,s3,s4,s5, ro) do { \
    float* op = oim + (ro) * OW; \
    float4 o; \
    o.x = cv[s2]; \
    o.y = fin(WD(h1,S14,s2)); o.z = fin(WD(h2,S14,s2)); o.w = fin(WD(h3,S14,s2)); \
    *(float4*)op = o; \
    o.x = fin(W1(cv,S7, s0,s1,s2,s3,s4,s5)); o.y = fin(W1(h1,S14,s0,s1,s2,s3,s4,s5)); \
    o.z = fin(W1(h2,S14,s0,s1,s2,s3,s4,s5)); o.w = fin(W1(h3,S14,s0,s1,s2,s3,s4,s5)); \
    *(float4*)(op + OW) = o; \
    o.x = fin(W2(cv,S7, s0,s1,s2,s3,s4,s5)); o.y = fin(W2(h1,S14,s0,s1,s2,s3,s4,s5)); \
    o.z = fin(W2(h2,S14,s0,s1,s2,s3,s4,s5)); o.w = fin(W2(h3,S14,s0,s1,s2,s3,s4,s5)); \
    *(float4*)(op + 2 * OW) = o; \
    o.x = fin(W3(cv,S7, s0,s1,s2,s3,s4,s5)); o.y = fin(W3(h1,S14,s0,s1,s2,s3,s4,s5)); \
    o.z = fin(W3(h2,S14,s0,s1,s2,s3,s4,s5)); o.w = fin(W3(h3,S14,s0,s1,s2,s3,s4,s5)); \
    *(float4*)(op + 3 * OW) = o; \
} while (0)

__global__ __launch_bounds__(240, 6)
void vtm_down_kernel(const float* __restrict__ x, float* __restrict__ out) {
    const int bc = blockIdx.y;            // image 0..23
    const int B  = blockIdx.x;            // 16-output-row chunk, 0..33

    __shared__ float xt[NRS][XCP];

    const int tid = threadIdx.x;          // 0..239 : output-col tile
    const float* xim = x + bc * (IH * IW);      // all offsets < 2^31
    const int r0 = 4 * B - 2;             // global input row of local 0

    // ---- stage 9 x 245 clamped input window ----
    const int c0 = tid - 2 < 0 ? 0 : tid - 2;   // left clamp (tid<2 only)
    #pragma unroll
    for (int r = 0; r < NRS; r++) {
        int gr = r0 + r; if (gr < 0) gr = 0;    // top clamp (B==0 only)
        const float* row = xim + gr * IW;
        xt[r][tid] = __ldg(&row[c0]);
        if (tid < XC - 240) xt[r][240 + tid] = __ldg(&row[238 + tid]);
    }
    __syncthreads();

    float cv[7], h1[7], h2[7], h3[7];
    float* oim = out + bc * (OH * OW) + (16 * B) * OW + tid * 4;

    // rows 0..5 -> slots 0..5, emit band0; row6 -> slot6, band1;
    // row7 -> slot0, band2; row8 -> slot1, band3 (skipped for B==33).
    HROW(0, 0); HROW(1, 1); HROW(2, 2); HROW(3, 3); HROW(4, 4); HROW(5, 5);
    BAND(0, 1, 2, 3, 4, 5, 0);
    HROW(6, 6);
    BAND(1, 2, 3, 4, 5, 6, 4);
    HROW(7, 0);
    BAND(2, 3, 4, 5, 6, 0, 8);
    if (B < 33) {
        HROW(8, 1);
        BAND(3, 4, 5, 6, 0, 1, 12);
    }
}

extern "C" void kernel_launch(void* const* d_in, const int* in_sizes, int n_in,
                              void* d_out, int out_size) {
    const float* x = (const float*)d_in[0];
    float* out = (float*)d_out;
    dim3 grid(34, NIMG);                  // 816 blocks <= 888 resident: one wave
    vtm_down_kernel<<<grid, 240>>>(x, out);
}